// round 16
// baseline (speedup 1.0000x reference)
#include <cuda_runtime.h>
#include <cuda_fp16.h>
#include <math.h>
#include <stdint.h>

#define NP 500000
#define NQ 200000
#define CDIM 64
#define EMAX 1200000

// padded sizes for the 1024-per-block scan
#define NQPAD 200704   // 196 * 1024
#define NPPAD 500736   // 489 * 1024
#define MQ 196
#define MP 489

// ------------------------- scratch (static device globals) -------------------------
__device__ __half g_hsP[(size_t)NP * CDIM];   // fp16 hs (both tables co-resident in L2)
__device__ __half g_hsQ[(size_t)NQ * CDIM];
__device__ __half g_hp1[(size_t)NP * CDIM];   // fp16 layer-0 outputs
__device__ __half g_hq1[(size_t)NQ * CDIM];
__device__ float g_alsP[NP], g_aldP[NP];
__device__ float g_alsQ[NQ], g_aldQ[NQ];
__device__ float g_wvec[256];   // 4 wvecs: [l*128 + conv*64 + k]
// CSR scratch
__device__ int g_cntQ[NQPAD], g_cntP[NPPAD];
__device__ int g_rowQ[NQPAD], g_rowP[NPPAD];
__device__ int g_curQ[NQPAD], g_curP[NPPAD];
__device__ int g_partQ[1024], g_partP[1024];
__device__ int g_ssrc0[EMAX];   // conv0 (P->Q): person srcs sorted by product dst
__device__ int g_ssrc1[EMAX];   // conv1 (Q->P): product srcs sorted by person dst

// ------------------------- f32x2 packed-FMA helpers -------------------------
__device__ __forceinline__ unsigned long long pack2(float lo, float hi) {
    unsigned long long r;
    asm("mov.b64 %0, {%1, %2};" : "=l"(r) : "f"(lo), "f"(hi));
    return r;
}
__device__ __forceinline__ void fma2(unsigned long long& acc, unsigned long long a,
                                     unsigned long long b) {
    asm("fma.rn.f32x2 %0, %1, %2, %0;" : "+l"(acc) : "l"(a), "l"(b));
}
__device__ __forceinline__ float2 unpack2(unsigned long long v) {
    float lo, hi;
    asm("mov.b64 {%0, %1}, %2;" : "=f"(lo), "=f"(hi) : "l"(v));
    return make_float2(lo, hi);
}

__device__ __forceinline__ float elu1(float v) { return (v > 0.f) ? v : expm1f(v); }

// ------------------------- CSR build kernels -------------------------
__global__ void hist_kernel(const int* __restrict__ pv_d, const int* __restrict__ vp_d,
                            int* __restrict__ cntQ, int* __restrict__ cntP, int E) {
    int i = blockIdx.x * blockDim.x + threadIdx.x;
    if (i < E) atomicAdd(&cntQ[__ldg(&pv_d[i])], 1);
    else if (i < 2 * E) atomicAdd(&cntP[__ldg(&vp_d[i - E])], 1);
}

// merged: blocks [0,MQ) scan cntQ; blocks [MQ,MQ+MP) scan cntP
__global__ void scan_local2_kernel(const int* __restrict__ cntQ, int* __restrict__ rowQ,
                                   int* __restrict__ partQ,
                                   const int* __restrict__ cntP, int* __restrict__ rowP,
                                   int* __restrict__ partP) {
    __shared__ int sm[256];
    const int* cnt; int* row; int* part; int b;
    if (blockIdx.x < MQ) { cnt = cntQ; row = rowQ; part = partQ; b = blockIdx.x; }
    else                 { cnt = cntP; row = rowP; part = partP; b = blockIdx.x - MQ; }
    int t = threadIdx.x;
    int base = b * 1024 + t * 4;
    int4 v = *(const int4*)(cnt + base);
    int tsum = v.x + v.y + v.z + v.w;
    sm[t] = tsum;
    __syncthreads();
    #pragma unroll
    for (int off = 1; off < 256; off <<= 1) {
        int add = (t >= off) ? sm[t - off] : 0;
        __syncthreads();
        sm[t] += add;
        __syncthreads();
    }
    int excl = sm[t] - tsum;
    int r1 = excl + v.x, r2 = r1 + v.y, r3 = r2 + v.z;
    *(int4*)(row + base) = make_int4(excl, r1, r2, r3);
    if (t == 255) part[b] = sm[255];
}

// merged: block 0 scans partQ (MQ entries), block 1 scans partP (MP entries)
__global__ void scan_part2_kernel(int* __restrict__ partQ, int* __restrict__ partP) {
    __shared__ int sm[1024];
    int* part = (blockIdx.x == 0) ? partQ : partP;
    int M     = (blockIdx.x == 0) ? MQ : MP;
    int t = threadIdx.x;
    int orig = (t < M) ? part[t] : 0;
    sm[t] = orig;
    __syncthreads();
    #pragma unroll
    for (int off = 1; off < 1024; off <<= 1) {
        int add = (t >= off) ? sm[t - off] : 0;
        __syncthreads();
        sm[t] += add;
        __syncthreads();
    }
    if (t < M) part[t] = sm[t] - orig;
}

// merged: i in [0,NQPAD) -> Q; [NQPAD, NQPAD+NPPAD) -> P
__global__ void scan_add2_kernel(int* __restrict__ rowQ, const int* __restrict__ partQ,
                                 int* __restrict__ curQ,
                                 int* __restrict__ rowP, const int* __restrict__ partP,
                                 int* __restrict__ curP) {
    int i = blockIdx.x * blockDim.x + threadIdx.x;
    if (i < NQPAD) {
        int r = rowQ[i] + __ldg(&partQ[i >> 10]);
        rowQ[i] = r;
        curQ[i] = r;
    } else if (i < NQPAD + NPPAD) {
        int j = i - NQPAD;
        int r = rowP[j] + __ldg(&partP[j >> 10]);
        rowP[j] = r;
        curP[j] = r;
    }
}

__global__ void scatter_kernel(const int* __restrict__ pv_s, const int* __restrict__ pv_d,
                               const int* __restrict__ vp_s, const int* __restrict__ vp_d,
                               int* __restrict__ curQ, int* __restrict__ curP,
                               int* __restrict__ ssrc0, int* __restrict__ ssrc1, int E) {
    int i = blockIdx.x * blockDim.x + threadIdx.x;
    if (i < E) {
        int pos = atomicAdd(&curQ[__ldg(&pv_d[i])], 1);
        ssrc0[pos] = __ldg(&pv_s[i]);
    } else if (i < 2 * E) {
        int j = i - E;
        int pos = atomicAdd(&curP[__ldg(&vp_d[j])], 1);
        ssrc1[pos] = __ldg(&vp_s[j]);
    }
}

// all 4 wvecs at once
__global__ void wvec4_kernel(const float* __restrict__ Wdst, const float* __restrict__ adst,
                             float* __restrict__ wvec) {
    int t = threadIdx.x;          // 0..255
    int idx = t >> 6;             // which (l,conv) 0..3
    int k = t & 63;
    const float* W = Wdst + (size_t)idx * 4096;
    const float* a = adst + idx * 64;
    float s = 0.f;
    #pragma unroll
    for (int c = 0; c < CDIM; c++) s = fmaf(W[k * CDIM + c], a[c], s);
    wvec[t] = s;
}

// ------------------------- GEMM body (templated X type) -------------------------
template <bool ELU, typename TX>
__device__ __forceinline__ void gemm_body(
    const TX* __restrict__ X, const float* __restrict__ W,
    const float* __restrict__ avs, const float* __restrict__ wvec,
    __half* __restrict__ H, float* __restrict__ als, float* __restrict__ ald,
    int N, int row0, float* xT, float* ws)
{
    const int tid = threadIdx.x;

    {
        const float4* Wv = (const float4*)W;
        float4* wsv = (float4*)ws;
        #pragma unroll
        for (int i = 0; i < 8; i++) wsv[i * 128 + tid] = Wv[i * 128 + tid];
    }
    {
        int row = row0 + tid;
        if (row < N) {
            if (sizeof(TX) == 4) {     // fp32 input
                const float4* Xv = (const float4*)(X + (size_t)row * CDIM);
                #pragma unroll
                for (int j = 0; j < 16; j++) {
                    float4 v = Xv[j];
                    if (ELU) {
                        v.x = elu1(v.x); v.y = elu1(v.y);
                        v.z = elu1(v.z); v.w = elu1(v.w);
                    }
                    xT[(4 * j + 0) * 128 + tid] = v.x;
                    xT[(4 * j + 1) * 128 + tid] = v.y;
                    xT[(4 * j + 2) * 128 + tid] = v.z;
                    xT[(4 * j + 3) * 128 + tid] = v.w;
                }
            } else {                   // fp16 input
                const uint4* Xv = (const uint4*)(X + (size_t)row * CDIM);
                #pragma unroll
                for (int j = 0; j < 8; j++) {
                    uint4 hv = Xv[j];
                    const half2* hh = (const half2*)&hv;
                    #pragma unroll
                    for (int q = 0; q < 4; q++) {
                        float2 f = __half22float2(hh[q]);
                        if (ELU) { f.x = elu1(f.x); f.y = elu1(f.y); }
                        xT[(8 * j + 2 * q + 0) * 128 + tid] = f.x;
                        xT[(8 * j + 2 * q + 1) * 128 + tid] = f.y;
                    }
                }
            }
        } else {
            #pragma unroll
            for (int j = 0; j < 64; j++) xT[j * 128 + tid] = 0.f;
        }
    }
    __syncthreads();

    const int ty = tid >> 3;
    const int tx = tid & 7;
    unsigned long long acc[8][4];
    #pragma unroll
    for (int i = 0; i < 8; i++)
        #pragma unroll
        for (int j = 0; j < 4; j++) acc[i][j] = 0ull;

    #pragma unroll 4
    for (int k = 0; k < 64; k++) {
        float4 a0 = *(const float4*)&xT[k * 128 + ty * 8];
        float4 a1 = *(const float4*)&xT[k * 128 + ty * 8 + 4];
        float4 b0 = *(const float4*)&ws[k * 64 + tx * 8];
        float4 b1 = *(const float4*)&ws[k * 64 + tx * 8 + 4];
        unsigned long long bp[4] = {pack2(b0.x, b0.y), pack2(b0.z, b0.w),
                                    pack2(b1.x, b1.y), pack2(b1.z, b1.w)};
        float a[8] = {a0.x, a0.y, a0.z, a0.w, a1.x, a1.y, a1.z, a1.w};
        #pragma unroll
        for (int i = 0; i < 8; i++) {
            unsigned long long ap = pack2(a[i], a[i]);
            #pragma unroll
            for (int j = 0; j < 4; j++) fma2(acc[i][j], ap, bp[j]);
        }
    }

    unsigned long long avp[4];
    {
        float4 av0 = __ldg((const float4*)avs + tx * 2);
        float4 av1 = __ldg((const float4*)avs + tx * 2 + 1);
        avp[0] = pack2(av0.x, av0.y); avp[1] = pack2(av0.z, av0.w);
        avp[2] = pack2(av1.x, av1.y); avp[3] = pack2(av1.z, av1.w);
    }

    #pragma unroll
    for (int i = 0; i < 8; i++) {
        int row = row0 + ty * 8 + i;
        unsigned long long alp = 0ull;
        #pragma unroll
        for (int j = 0; j < 4; j++) fma2(alp, acc[i][j], avp[j]);
        float2 f = unpack2(alp);
        float al = f.x + f.y;
        al += __shfl_down_sync(0xffffffffu, al, 4);
        al += __shfl_down_sync(0xffffffffu, al, 2);
        al += __shfl_down_sync(0xffffffffu, al, 1);
        if (row < N) {
            half2 p0 = __float22half2_rn(unpack2(acc[i][0]));
            half2 p1 = __float22half2_rn(unpack2(acc[i][1]));
            half2 p2 = __float22half2_rn(unpack2(acc[i][2]));
            half2 p3 = __float22half2_rn(unpack2(acc[i][3]));
            uint4 hv;
            hv.x = *reinterpret_cast<unsigned*>(&p0);
            hv.y = *reinterpret_cast<unsigned*>(&p1);
            hv.z = *reinterpret_cast<unsigned*>(&p2);
            hv.w = *reinterpret_cast<unsigned*>(&p3);
            ((uint4*)(H + (size_t)row * CDIM))[tx] = hv;
            if (tx == 0) als[row] = al;
        }
    }

    {
        float s = 0.f;
        #pragma unroll
        for (int k = 0; k < 64; k++) s = fmaf(xT[k * 128 + tid], __ldg(&wvec[k]), s);
        int row = row0 + tid;
        if (row < N) ald[row] = s;
    }
}

// merged GEMM: blocks [0,gP) = person side; [gP, gP+gQ) = product side
template <bool ELU, typename TX>
__global__ __launch_bounds__(128) void gemm2_kernel(
    const TX* __restrict__ Xp, const float* __restrict__ Wp,
    const float* __restrict__ avsp, const float* __restrict__ wvp,
    __half* __restrict__ Hp, float* __restrict__ alsP, float* __restrict__ aldP,
    int gPblocks,
    const TX* __restrict__ Xq, const float* __restrict__ Wq,
    const float* __restrict__ avsq, const float* __restrict__ wvq,
    __half* __restrict__ Hq, float* __restrict__ alsQ, float* __restrict__ aldQ)
{
    __shared__ float xT[64 * 128];
    __shared__ float ws[64 * 64];
    if ((int)blockIdx.x < gPblocks) {
        gemm_body<ELU, TX>(Xp, Wp, avsp, wvp, Hp, alsP, aldP, NP,
                           blockIdx.x * 128, xT, ws);
    } else {
        gemm_body<ELU, TX>(Xq, Wq, avsq, wvq, Hq, alsQ, aldQ, NQ,
                           (blockIdx.x - gPblocks) * 128, xT, ws);
    }
}

// ---- GAT body: 4 rows/warp, fp16 hs gather, deferred den reduce, x4 unroll ----
template <bool ELUOUT, typename TOUT>
__device__ __forceinline__ void gat_body(
    const int* __restrict__ row, const int* __restrict__ cnt, const int* __restrict__ ssrc,
    const float* __restrict__ als, const float* __restrict__ ald,
    const __half* __restrict__ hs, const float* __restrict__ bias,
    TOUT* __restrict__ out, int Nd, int w)
{
    const unsigned FULL = 0xffffffffu;
    int r0 = w * 4;
    if (r0 >= Nd) return;
    const int lane = threadIdx.x & 31;
    const int qg   = lane >> 3;      // which row of the quad (0..3)
    const int part = lane & 7;       // 8-channel slice

    int myrow = r0 + qg;
    bool rowvalid = (myrow < Nd);
    int myr = rowvalid ? myrow : r0;
    int start = __ldg(&row[myr]);
    int deg   = rowvalid ? __ldg(&cnt[myr]) : 0;
    float aldv = __ldg(&ald[myr]);
    float4 res0 = __ldg((const float4*)bias + part * 2);
    float4 res1 = __ldg((const float4*)bias + part * 2 + 1);

    int degmax = max(deg, __shfl_xor_sync(FULL, deg, 8));
    degmax = max(degmax, __shfl_xor_sync(FULL, degmax, 16));

    float4 acc0 = make_float4(0.f, 0.f, 0.f, 0.f);
    float4 acc1 = make_float4(0.f, 0.f, 0.f, 0.f);
    float exsum = 0.f;   // per-lane partial den (reduced once at the end)
    for (int c0 = 0; c0 < degmax; c0 += 8) {
        int e = c0 + part;
        int s = 0; float ex = 0.f;
        if (e < deg) {
            s = __ldg(&ssrc[start + e]);
            float v = __ldg(&als[s]) + aldv;
            v = (v >= 0.f) ? v : 0.2f * v;
            ex = __expf(fminf(v, 80.f));
        }
        exsum += ex;

        int m = min(8, degmax - c0);
        int j = 0;
        for (; j + 4 <= m; j += 4) {
            int   s0 = __shfl_sync(FULL, s,  j,     8);
            int   s1 = __shfl_sync(FULL, s,  j + 1, 8);
            int   s2 = __shfl_sync(FULL, s,  j + 2, 8);
            int   s3 = __shfl_sync(FULL, s,  j + 3, 8);
            float a0 = __shfl_sync(FULL, ex, j,     8);
            float a1 = __shfl_sync(FULL, ex, j + 1, 8);
            float a2 = __shfl_sync(FULL, ex, j + 2, 8);
            float a3 = __shfl_sync(FULL, ex, j + 3, 8);
            uint4 hv0 = __ldg((const uint4*)(hs + (size_t)s0 * CDIM) + part);
            uint4 hv1 = __ldg((const uint4*)(hs + (size_t)s1 * CDIM) + part);
            uint4 hv2 = __ldg((const uint4*)(hs + (size_t)s2 * CDIM) + part);
            uint4 hv3 = __ldg((const uint4*)(hs + (size_t)s3 * CDIM) + part);
            {
                half2* hh = (half2*)&hv0;
                float2 f0 = __half22float2(hh[0]);
                float2 f1 = __half22float2(hh[1]);
                float2 f2 = __half22float2(hh[2]);
                float2 f3 = __half22float2(hh[3]);
                acc0.x = fmaf(a0, f0.x, acc0.x); acc0.y = fmaf(a0, f0.y, acc0.y);
                acc0.z = fmaf(a0, f1.x, acc0.z); acc0.w = fmaf(a0, f1.y, acc0.w);
                acc1.x = fmaf(a0, f2.x, acc1.x); acc1.y = fmaf(a0, f2.y, acc1.y);
                acc1.z = fmaf(a0, f3.x, acc1.z); acc1.w = fmaf(a0, f3.y, acc1.w);
            }
            {
                half2* hh = (half2*)&hv1;
                float2 f0 = __half22float2(hh[0]);
                float2 f1 = __half22float2(hh[1]);
                float2 f2 = __half22float2(hh[2]);
                float2 f3 = __half22float2(hh[3]);
                acc0.x = fmaf(a1, f0.x, acc0.x); acc0.y = fmaf(a1, f0.y, acc0.y);
                acc0.z = fmaf(a1, f1.x, acc0.z); acc0.w = fmaf(a1, f1.y, acc0.w);
                acc1.x = fmaf(a1, f2.x, acc1.x); acc1.y = fmaf(a1, f2.y, acc1.y);
                acc1.z = fmaf(a1, f3.x, acc1.z); acc1.w = fmaf(a1, f3.y, acc1.w);
            }
            {
                half2* hh = (half2*)&hv2;
                float2 f0 = __half22float2(hh[0]);
                float2 f1 = __half22float2(hh[1]);
                float2 f2 = __half22float2(hh[2]);
                float2 f3 = __half22float2(hh[3]);
                acc0.x = fmaf(a2, f0.x, acc0.x); acc0.y = fmaf(a2, f0.y, acc0.y);
                acc0.z = fmaf(a2, f1.x, acc0.z); acc0.w = fmaf(a2, f1.y, acc0.w);
                acc1.x = fmaf(a2, f2.x, acc1.x); acc1.y = fmaf(a2, f2.y, acc1.y);
                acc1.z = fmaf(a2, f3.x, acc1.z); acc1.w = fmaf(a2, f3.y, acc1.w);
            }
            {
                half2* hh = (half2*)&hv3;
                float2 f0 = __half22float2(hh[0]);
                float2 f1 = __half22float2(hh[1]);
                float2 f2 = __half22float2(hh[2]);
                float2 f3 = __half22float2(hh[3]);
                acc0.x = fmaf(a3, f0.x, acc0.x); acc0.y = fmaf(a3, f0.y, acc0.y);
                acc0.z = fmaf(a3, f1.x, acc0.z); acc0.w = fmaf(a3, f1.y, acc0.w);
                acc1.x = fmaf(a3, f2.x, acc1.x); acc1.y = fmaf(a3, f2.y, acc1.y);
                acc1.z = fmaf(a3, f3.x, acc1.z); acc1.w = fmaf(a3, f3.y, acc1.w);
            }
        }
        for (; j < m; j++) {
            int   s0 = __shfl_sync(FULL, s,  j, 8);
            float a0 = __shfl_sync(FULL, ex, j, 8);
            uint4 hv0 = __ldg((const uint4*)(hs + (size_t)s0 * CDIM) + part);
            half2* hh = (half2*)&hv0;
            float2 f0 = __half22float2(hh[0]);
            float2 f1 = __half22float2(hh[1]);
            float2 f2 = __half22float2(hh[2]);
            float2 f3 = __half22float2(hh[3]);
            acc0.x = fmaf(a0, f0.x, acc0.x); acc0.y = fmaf(a0, f0.y, acc0.y);
            acc0.z = fmaf(a0, f1.x, acc0.z); acc0.w = fmaf(a0, f1.y, acc0.w);
            acc1.x = fmaf(a0, f2.x, acc1.x); acc1.y = fmaf(a0, f2.y, acc1.y);
            acc1.z = fmaf(a0, f3.x, acc1.z); acc1.w = fmaf(a0, f3.y, acc1.w);
        }
    }
    // deferred den reduction over the 8-lane group
    float den = exsum;
    #pragma unroll
    for (int off = 4; off > 0; off >>= 1) den += __shfl_xor_sync(FULL, den, off, 8);

    float inv = (den > 0.f) ? (1.f / den) : 0.f;
    res0.x = fmaf(acc0.x, inv, res0.x); res0.y = fmaf(acc0.y, inv, res0.y);
    res0.z = fmaf(acc0.z, inv, res0.z); res0.w = fmaf(acc0.w, inv, res0.w);
    res1.x = fmaf(acc1.x, inv, res1.x); res1.y = fmaf(acc1.y, inv, res1.y);
    res1.z = fmaf(acc1.z, inv, res1.z); res1.w = fmaf(acc1.w, inv, res1.w);

    if (ELUOUT) {
        res0.x = elu1(res0.x); res0.y = elu1(res0.y);
        res0.z = elu1(res0.z); res0.w = elu1(res0.w);
        res1.x = elu1(res1.x); res1.y = elu1(res1.y);
        res1.z = elu1(res1.z); res1.w = elu1(res1.w);
    }
    if (rowvalid) {
        if (sizeof(TOUT) == 4) {    // fp32 output (final layer)
            float4* op = (float4*)((float*)out + (size_t)myrow * CDIM);
            op[part * 2]     = res0;
            op[part * 2 + 1] = res1;
        } else {                    // fp16 output (intermediate)
            half2 p0 = __float22half2_rn(make_float2(res0.x, res0.y));
            half2 p1 = __float22half2_rn(make_float2(res0.z, res0.w));
            half2 p2 = __float22half2_rn(make_float2(res1.x, res1.y));
            half2 p3 = __float22half2_rn(make_float2(res1.z, res1.w));
            uint4 hv;
            hv.x = *reinterpret_cast<unsigned*>(&p0);
            hv.y = *reinterpret_cast<unsigned*>(&p1);
            hv.z = *reinterpret_cast<unsigned*>(&p2);
            hv.w = *reinterpret_cast<unsigned*>(&p3);
            ((uint4*)((__half*)out + (size_t)myrow * CDIM))[part] = hv;
        }
    }
}

// merged GAT: warps [0,nwP) = person-dst conv (conv1); [nwP, ...) = product-dst (conv0)
template <bool ELUOUT, typename TOUT>
__global__ __launch_bounds__(256) void gat2_kernel(
    const int* __restrict__ rowP, const int* __restrict__ cntP, const int* __restrict__ ssrc1,
    const float* __restrict__ alsQ, const float* __restrict__ aldP,
    const __half* __restrict__ hsQ, const float* __restrict__ biasP,
    TOUT* __restrict__ outP, int nwP,
    const int* __restrict__ rowQ, const int* __restrict__ cntQ, const int* __restrict__ ssrc0,
    const float* __restrict__ alsP, const float* __restrict__ aldQ,
    const __half* __restrict__ hsP, const float* __restrict__ biasQ,
    TOUT* __restrict__ outQ)
{
    int w = (blockIdx.x * blockDim.x + threadIdx.x) >> 5;
    if (w < nwP) {
        gat_body<ELUOUT, TOUT>(rowP, cntP, ssrc1, alsQ, aldP, hsQ, biasP, outP, NP, w);
    } else {
        gat_body<ELUOUT, TOUT>(rowQ, cntQ, ssrc0, alsP, aldQ, hsP, biasQ, outQ, NQ, w - nwP);
    }
}

// ------------------------- host orchestration -------------------------
extern "C" void kernel_launch(void* const* d_in, const int* in_sizes, int n_in,
                              void* d_out, int out_size)
{
    const float* xp   = (const float*)d_in[0];
    const float* xq   = (const float*)d_in[1];
    const int*   pv_s = (const int*)d_in[2];
    const int*   pv_d = (const int*)d_in[3];
    const int*   vp_s = (const int*)d_in[4];
    const int*   vp_d = (const int*)d_in[5];
    const float* Wsrc = (const float*)d_in[6];
    const float* Wdst = (const float*)d_in[7];
    const float* asrc = (const float*)d_in[8];
    const float* adst = (const float*)d_in[9];
    const float* bias = (const float*)d_in[10];
    int E = in_sizes[2];

    __half *hsP, *hsQ, *hp1, *hq1;
    float *alsP, *aldP, *alsQ, *aldQ, *wvec;
    int *cntQ, *cntP, *rowQ, *rowP, *curQ, *curP, *partQ, *partP, *ssrc0, *ssrc1;
    cudaGetSymbolAddress((void**)&hsP,   g_hsP);
    cudaGetSymbolAddress((void**)&hsQ,   g_hsQ);
    cudaGetSymbolAddress((void**)&hp1,   g_hp1);
    cudaGetSymbolAddress((void**)&hq1,   g_hq1);
    cudaGetSymbolAddress((void**)&alsP,  g_alsP);
    cudaGetSymbolAddress((void**)&aldP,  g_aldP);
    cudaGetSymbolAddress((void**)&alsQ,  g_alsQ);
    cudaGetSymbolAddress((void**)&aldQ,  g_aldQ);
    cudaGetSymbolAddress((void**)&wvec,  g_wvec);
    cudaGetSymbolAddress((void**)&cntQ,  g_cntQ);
    cudaGetSymbolAddress((void**)&cntP,  g_cntP);
    cudaGetSymbolAddress((void**)&rowQ,  g_rowQ);
    cudaGetSymbolAddress((void**)&rowP,  g_rowP);
    cudaGetSymbolAddress((void**)&curQ,  g_curQ);
    cudaGetSymbolAddress((void**)&curP,  g_curP);
    cudaGetSymbolAddress((void**)&partQ, g_partQ);
    cudaGetSymbolAddress((void**)&partP, g_partP);
    cudaGetSymbolAddress((void**)&ssrc0, g_ssrc0);
    cudaGetSymbolAddress((void**)&ssrc1, g_ssrc1);

    float* outp = (float*)d_out;
    float* outq = (float*)d_out + (size_t)NP * CDIM;

    const int gP = (NP + 127) / 128, gQ = (NQ + 127) / 128;
    const int nwP = (NP + 3) / 4, nwQ = (NQ + 3) / 4;
    const unsigned gG = (unsigned)(((long)(nwP + nwQ) * 32 + 255) / 256);
    const unsigned gE2 = (2 * E + 255) / 256;

    // side stream + events (host resources, created once; no device allocs)
    static cudaStream_t sideS = nullptr;
    static cudaEvent_t evFork = nullptr, evCsr = nullptr;
    if (sideS == nullptr) {
        cudaStreamCreateWithFlags(&sideS, cudaStreamNonBlocking);
        cudaEventCreateWithFlags(&evFork, cudaEventDisableTiming);
        cudaEventCreateWithFlags(&evCsr,  cudaEventDisableTiming);
    }
    cudaStream_t s0 = 0;   // origin (harness-captured) stream

    // fork: CSR build chain on side stream (independent of GEMM-L0)
    cudaEventRecord(evFork, s0);
    cudaStreamWaitEvent(sideS, evFork, 0);
    cudaMemsetAsync(cntQ, 0, (size_t)NQPAD * sizeof(int), sideS);
    cudaMemsetAsync(cntP, 0, (size_t)NPPAD * sizeof(int), sideS);
    hist_kernel<<<gE2, 256, 0, sideS>>>(pv_d, vp_d, cntQ, cntP, E);
    scan_local2_kernel<<<MQ + MP, 256, 0, sideS>>>(cntQ, rowQ, partQ, cntP, rowP, partP);
    scan_part2_kernel<<<2, 1024, 0, sideS>>>(partQ, partP);
    scan_add2_kernel<<<(NQPAD + NPPAD + 255) / 256, 256, 0, sideS>>>(rowQ, partQ, curQ,
                                                                     rowP, partP, curP);
    scatter_kernel<<<gE2, 256, 0, sideS>>>(pv_s, pv_d, vp_s, vp_d, curQ, curP, ssrc0, ssrc1, E);
    cudaEventRecord(evCsr, sideS);

    // main: wvecs + layer-0 GEMM (overlaps the CSR chain)
    wvec4_kernel<<<1, 256, 0, s0>>>(Wdst, adst, wvec);
    gemm2_kernel<false, float><<<gP + gQ, 128, 0, s0>>>(
        xp, Wsrc + 0 * 4096, asrc + 0 * 64, wvec + 64, hsP, alsP, aldP, gP,
        xq, Wsrc + 1 * 4096, asrc + 1 * 64, wvec,      hsQ, alsQ, aldQ);

    // join: gat needs both the CSR and GEMM-L0 results
    cudaStreamWaitEvent(s0, evCsr, 0);
    gat2_kernel<false, __half><<<gG, 256, 0, s0>>>(
        rowP, cntP, ssrc1, alsQ, aldP, hsQ, bias + 1 * 64, hp1, nwP,
        rowQ, cntQ, ssrc0, alsP, aldQ, hsP, bias + 0 * 64, hq1);

    // ---- layer 1: fp16 intermediates (ELU on load) -> fp32 outputs (ELU on store) ----
    gemm2_kernel<true, __half><<<gP + gQ, 128, 0, s0>>>(
        hp1, Wsrc + 2 * 4096, asrc + 2 * 64, wvec + 128 + 64, hsP, alsP, aldP, gP,
        hq1, Wsrc + 3 * 4096, asrc + 3 * 64, wvec + 128,      hsQ, alsQ, aldQ);
    gat2_kernel<true, float><<<gG, 256, 0, s0>>>(
        rowP, cntP, ssrc1, alsQ, aldP, hsQ, bias + 3 * 64, outp, nwP,
        rowQ, cntQ, ssrc0, alsP, aldQ, hsP, bias + 2 * 64, outq);
}

// round 17
// speedup vs baseline: 1.0693x; 1.0693x over previous
#include <cuda_runtime.h>
#include <cuda_fp16.h>
#include <math.h>
#include <stdint.h>

#define NP 500000
#define NQ 200000
#define CDIM 64
#define EMAX 1200000

// padded sizes for the 1024-per-block scan
#define NQPAD 200704   // 196 * 1024
#define NPPAD 500736   // 489 * 1024
#define MQ 196
#define MP 489

// ------------------------- scratch (static device globals) -------------------------
__device__ __half g_hsP[(size_t)NP * CDIM];   // fp16 hs (both tables co-resident in L2)
__device__ __half g_hsQ[(size_t)NQ * CDIM];
__device__ __half g_hp1[(size_t)NP * CDIM];   // fp16 layer-0 outputs
__device__ __half g_hq1[(size_t)NQ * CDIM];
__device__ float g_alsP[NP], g_aldP[NP];
__device__ float g_alsQ[NQ], g_aldQ[NQ];
__device__ float g_wvec[256];   // 4 wvecs: [l*128 + conv*64 + k]
// CSR scratch
__device__ int g_cntQ[NQPAD], g_cntP[NPPAD];
__device__ int g_rowQ[NQPAD], g_rowP[NPPAD];
__device__ int g_curQ[NQPAD], g_curP[NPPAD];
__device__ int g_partQ[1024], g_partP[1024];
__device__ int g_ssrc0[EMAX];   // conv0 (P->Q): person srcs sorted by product dst
__device__ int g_ssrc1[EMAX];   // conv1 (Q->P): product srcs sorted by person dst

// ------------------------- f32x2 packed-FMA helpers -------------------------
__device__ __forceinline__ unsigned long long pack2(float lo, float hi) {
    unsigned long long r;
    asm("mov.b64 %0, {%1, %2};" : "=l"(r) : "f"(lo), "f"(hi));
    return r;
}
__device__ __forceinline__ void fma2(unsigned long long& acc, unsigned long long a,
                                     unsigned long long b) {
    asm("fma.rn.f32x2 %0, %1, %2, %0;" : "+l"(acc) : "l"(a), "l"(b));
}
__device__ __forceinline__ float2 unpack2(unsigned long long v) {
    float lo, hi;
    asm("mov.b64 {%0, %1}, %2;" : "=f"(lo), "=f"(hi) : "l"(v));
    return make_float2(lo, hi);
}

__device__ __forceinline__ float elu1(float v) { return (v > 0.f) ? v : expm1f(v); }

// ------------------------- CSR build kernels -------------------------
__global__ void hist_kernel(const int* __restrict__ pv_d, const int* __restrict__ vp_d,
                            int* __restrict__ cntQ, int* __restrict__ cntP, int E) {
    int i = blockIdx.x * blockDim.x + threadIdx.x;
    if (i < E) atomicAdd(&cntQ[__ldg(&pv_d[i])], 1);
    else if (i < 2 * E) atomicAdd(&cntP[__ldg(&vp_d[i - E])], 1);
}

// merged: blocks [0,MQ) scan cntQ; blocks [MQ,MQ+MP) scan cntP
__global__ void scan_local2_kernel(const int* __restrict__ cntQ, int* __restrict__ rowQ,
                                   int* __restrict__ partQ,
                                   const int* __restrict__ cntP, int* __restrict__ rowP,
                                   int* __restrict__ partP) {
    __shared__ int sm[256];
    const int* cnt; int* row; int* part; int b;
    if (blockIdx.x < MQ) { cnt = cntQ; row = rowQ; part = partQ; b = blockIdx.x; }
    else                 { cnt = cntP; row = rowP; part = partP; b = blockIdx.x - MQ; }
    int t = threadIdx.x;
    int base = b * 1024 + t * 4;
    int4 v = *(const int4*)(cnt + base);
    int tsum = v.x + v.y + v.z + v.w;
    sm[t] = tsum;
    __syncthreads();
    #pragma unroll
    for (int off = 1; off < 256; off <<= 1) {
        int add = (t >= off) ? sm[t - off] : 0;
        __syncthreads();
        sm[t] += add;
        __syncthreads();
    }
    int excl = sm[t] - tsum;
    int r1 = excl + v.x, r2 = r1 + v.y, r3 = r2 + v.z;
    *(int4*)(row + base) = make_int4(excl, r1, r2, r3);
    if (t == 255) part[b] = sm[255];
}

// merged: block 0 scans partQ (MQ entries), block 1 scans partP (MP entries)
__global__ void scan_part2_kernel(int* __restrict__ partQ, int* __restrict__ partP) {
    __shared__ int sm[1024];
    int* part = (blockIdx.x == 0) ? partQ : partP;
    int M     = (blockIdx.x == 0) ? MQ : MP;
    int t = threadIdx.x;
    int orig = (t < M) ? part[t] : 0;
    sm[t] = orig;
    __syncthreads();
    #pragma unroll
    for (int off = 1; off < 1024; off <<= 1) {
        int add = (t >= off) ? sm[t - off] : 0;
        __syncthreads();
        sm[t] += add;
        __syncthreads();
    }
    if (t < M) part[t] = sm[t] - orig;
}

// merged: i in [0,NQPAD) -> Q; [NQPAD, NQPAD+NPPAD) -> P
__global__ void scan_add2_kernel(int* __restrict__ rowQ, const int* __restrict__ partQ,
                                 int* __restrict__ curQ,
                                 int* __restrict__ rowP, const int* __restrict__ partP,
                                 int* __restrict__ curP) {
    int i = blockIdx.x * blockDim.x + threadIdx.x;
    if (i < NQPAD) {
        int r = rowQ[i] + __ldg(&partQ[i >> 10]);
        rowQ[i] = r;
        curQ[i] = r;
    } else if (i < NQPAD + NPPAD) {
        int j = i - NQPAD;
        int r = rowP[j] + __ldg(&partP[j >> 10]);
        rowP[j] = r;
        curP[j] = r;
    }
}

__global__ void scatter_kernel(const int* __restrict__ pv_s, const int* __restrict__ pv_d,
                               const int* __restrict__ vp_s, const int* __restrict__ vp_d,
                               int* __restrict__ curQ, int* __restrict__ curP,
                               int* __restrict__ ssrc0, int* __restrict__ ssrc1, int E) {
    int i = blockIdx.x * blockDim.x + threadIdx.x;
    if (i < E) {
        int pos = atomicAdd(&curQ[__ldg(&pv_d[i])], 1);
        ssrc0[pos] = __ldg(&pv_s[i]);
    } else if (i < 2 * E) {
        int j = i - E;
        int pos = atomicAdd(&curP[__ldg(&vp_d[j])], 1);
        ssrc1[pos] = __ldg(&vp_s[j]);
    }
}

// all 4 wvecs at once
__global__ void wvec4_kernel(const float* __restrict__ Wdst, const float* __restrict__ adst,
                             float* __restrict__ wvec) {
    int t = threadIdx.x;          // 0..255
    int idx = t >> 6;             // which (l,conv) 0..3
    int k = t & 63;
    const float* W = Wdst + (size_t)idx * 4096;
    const float* a = adst + idx * 64;
    float s = 0.f;
    #pragma unroll
    for (int c = 0; c < CDIM; c++) s = fmaf(W[k * CDIM + c], a[c], s);
    wvec[t] = s;
}

// ------------------------- GEMM body (templated X type) -------------------------
template <bool ELU, typename TX>
__device__ __forceinline__ void gemm_body(
    const TX* __restrict__ X, const float* __restrict__ W,
    const float* __restrict__ avs, const float* __restrict__ wvec,
    __half* __restrict__ H, float* __restrict__ als, float* __restrict__ ald,
    int N, int row0, float* xT, float* ws)
{
    const int tid = threadIdx.x;

    {
        const float4* Wv = (const float4*)W;
        float4* wsv = (float4*)ws;
        #pragma unroll
        for (int i = 0; i < 8; i++) wsv[i * 128 + tid] = Wv[i * 128 + tid];
    }
    {
        int row = row0 + tid;
        if (row < N) {
            if (sizeof(TX) == 4) {     // fp32 input
                const float4* Xv = (const float4*)(X + (size_t)row * CDIM);
                #pragma unroll
                for (int j = 0; j < 16; j++) {
                    float4 v = Xv[j];
                    if (ELU) {
                        v.x = elu1(v.x); v.y = elu1(v.y);
                        v.z = elu1(v.z); v.w = elu1(v.w);
                    }
                    xT[(4 * j + 0) * 128 + tid] = v.x;
                    xT[(4 * j + 1) * 128 + tid] = v.y;
                    xT[(4 * j + 2) * 128 + tid] = v.z;
                    xT[(4 * j + 3) * 128 + tid] = v.w;
                }
            } else {                   // fp16 input
                const uint4* Xv = (const uint4*)(X + (size_t)row * CDIM);
                #pragma unroll
                for (int j = 0; j < 8; j++) {
                    uint4 hv = Xv[j];
                    const half2* hh = (const half2*)&hv;
                    #pragma unroll
                    for (int q = 0; q < 4; q++) {
                        float2 f = __half22float2(hh[q]);
                        if (ELU) { f.x = elu1(f.x); f.y = elu1(f.y); }
                        xT[(8 * j + 2 * q + 0) * 128 + tid] = f.x;
                        xT[(8 * j + 2 * q + 1) * 128 + tid] = f.y;
                    }
                }
            }
        } else {
            #pragma unroll
            for (int j = 0; j < 64; j++) xT[j * 128 + tid] = 0.f;
        }
    }
    __syncthreads();

    const int ty = tid >> 3;
    const int tx = tid & 7;
    unsigned long long acc[8][4];
    #pragma unroll
    for (int i = 0; i < 8; i++)
        #pragma unroll
        for (int j = 0; j < 4; j++) acc[i][j] = 0ull;

    #pragma unroll 4
    for (int k = 0; k < 64; k++) {
        float4 a0 = *(const float4*)&xT[k * 128 + ty * 8];
        float4 a1 = *(const float4*)&xT[k * 128 + ty * 8 + 4];
        float4 b0 = *(const float4*)&ws[k * 64 + tx * 8];
        float4 b1 = *(const float4*)&ws[k * 64 + tx * 8 + 4];
        unsigned long long bp[4] = {pack2(b0.x, b0.y), pack2(b0.z, b0.w),
                                    pack2(b1.x, b1.y), pack2(b1.z, b1.w)};
        float a[8] = {a0.x, a0.y, a0.z, a0.w, a1.x, a1.y, a1.z, a1.w};
        #pragma unroll
        for (int i = 0; i < 8; i++) {
            unsigned long long ap = pack2(a[i], a[i]);
            #pragma unroll
            for (int j = 0; j < 4; j++) fma2(acc[i][j], ap, bp[j]);
        }
    }

    unsigned long long avp[4];
    {
        float4 av0 = __ldg((const float4*)avs + tx * 2);
        float4 av1 = __ldg((const float4*)avs + tx * 2 + 1);
        avp[0] = pack2(av0.x, av0.y); avp[1] = pack2(av0.z, av0.w);
        avp[2] = pack2(av1.x, av1.y); avp[3] = pack2(av1.z, av1.w);
    }

    #pragma unroll
    for (int i = 0; i < 8; i++) {
        int row = row0 + ty * 8 + i;
        unsigned long long alp = 0ull;
        #pragma unroll
        for (int j = 0; j < 4; j++) fma2(alp, acc[i][j], avp[j]);
        float2 f = unpack2(alp);
        float al = f.x + f.y;
        al += __shfl_down_sync(0xffffffffu, al, 4);
        al += __shfl_down_sync(0xffffffffu, al, 2);
        al += __shfl_down_sync(0xffffffffu, al, 1);
        if (row < N) {
            half2 p0 = __float22half2_rn(unpack2(acc[i][0]));
            half2 p1 = __float22half2_rn(unpack2(acc[i][1]));
            half2 p2 = __float22half2_rn(unpack2(acc[i][2]));
            half2 p3 = __float22half2_rn(unpack2(acc[i][3]));
            uint4 hv;
            hv.x = *reinterpret_cast<unsigned*>(&p0);
            hv.y = *reinterpret_cast<unsigned*>(&p1);
            hv.z = *reinterpret_cast<unsigned*>(&p2);
            hv.w = *reinterpret_cast<unsigned*>(&p3);
            ((uint4*)(H + (size_t)row * CDIM))[tx] = hv;
            if (tx == 0) als[row] = al;
        }
    }

    {
        float s = 0.f;
        #pragma unroll
        for (int k = 0; k < 64; k++) s = fmaf(xT[k * 128 + tid], __ldg(&wvec[k]), s);
        int row = row0 + tid;
        if (row < N) ald[row] = s;
    }
}

// merged GEMM: blocks [0,gP) = person side; [gP, gP+gQ) = product side
template <bool ELU, typename TX>
__global__ __launch_bounds__(128) void gemm2_kernel(
    const TX* __restrict__ Xp, const float* __restrict__ Wp,
    const float* __restrict__ avsp, const float* __restrict__ wvp,
    __half* __restrict__ Hp, float* __restrict__ alsP, float* __restrict__ aldP,
    int gPblocks,
    const TX* __restrict__ Xq, const float* __restrict__ Wq,
    const float* __restrict__ avsq, const float* __restrict__ wvq,
    __half* __restrict__ Hq, float* __restrict__ alsQ, float* __restrict__ aldQ)
{
    __shared__ float xT[64 * 128];
    __shared__ float ws[64 * 64];
    if ((int)blockIdx.x < gPblocks) {
        gemm_body<ELU, TX>(Xp, Wp, avsp, wvp, Hp, alsP, aldP, NP,
                           blockIdx.x * 128, xT, ws);
    } else {
        gemm_body<ELU, TX>(Xq, Wq, avsq, wvq, Hq, alsQ, aldQ, NQ,
                           (blockIdx.x - gPblocks) * 128, xT, ws);
    }
}

// ---- GAT body: 4 rows/warp, fp16 hs gather, x2 unroll, deferred den reduce ----
template <bool ELUOUT, typename TOUT>
__device__ __forceinline__ void gat_body(
    const int* __restrict__ row, const int* __restrict__ cnt, const int* __restrict__ ssrc,
    const float* __restrict__ als, const float* __restrict__ ald,
    const __half* __restrict__ hs, const float* __restrict__ bias,
    TOUT* __restrict__ out, int Nd, int w)
{
    const unsigned FULL = 0xffffffffu;
    int r0 = w * 4;
    if (r0 >= Nd) return;
    const int lane = threadIdx.x & 31;
    const int qg   = lane >> 3;      // which row of the quad (0..3)
    const int part = lane & 7;       // 8-channel slice

    int myrow = r0 + qg;
    bool rowvalid = (myrow < Nd);
    int myr = rowvalid ? myrow : r0;
    int start = __ldg(&row[myr]);
    int deg   = rowvalid ? __ldg(&cnt[myr]) : 0;
    float aldv = __ldg(&ald[myr]);
    float4 res0 = __ldg((const float4*)bias + part * 2);
    float4 res1 = __ldg((const float4*)bias + part * 2 + 1);

    int degmax = max(deg, __shfl_xor_sync(FULL, deg, 8));
    degmax = max(degmax, __shfl_xor_sync(FULL, degmax, 16));

    float4 acc0 = make_float4(0.f, 0.f, 0.f, 0.f);
    float4 acc1 = make_float4(0.f, 0.f, 0.f, 0.f);
    float exsum = 0.f;   // per-lane partial den (reduced once at the end)
    for (int c0 = 0; c0 < degmax; c0 += 8) {
        int e = c0 + part;
        int s = 0; float ex = 0.f;
        if (e < deg) {
            s = __ldg(&ssrc[start + e]);
            float v = __ldg(&als[s]) + aldv;
            v = (v >= 0.f) ? v : 0.2f * v;
            ex = __expf(fminf(v, 80.f));
        }
        exsum += ex;

        int m = min(8, degmax - c0);
        int j = 0;
        for (; j + 2 <= m; j += 2) {
            int   s0 = __shfl_sync(FULL, s,  j,     8);
            float a0 = __shfl_sync(FULL, ex, j,     8);
            int   s1 = __shfl_sync(FULL, s,  j + 1, 8);
            float a1 = __shfl_sync(FULL, ex, j + 1, 8);
            uint4 hv0 = __ldg((const uint4*)(hs + (size_t)s0 * CDIM) + part);
            uint4 hv1 = __ldg((const uint4*)(hs + (size_t)s1 * CDIM) + part);
            {
                half2* hh = (half2*)&hv0;
                float2 f0 = __half22float2(hh[0]);
                float2 f1 = __half22float2(hh[1]);
                float2 f2 = __half22float2(hh[2]);
                float2 f3 = __half22float2(hh[3]);
                acc0.x = fmaf(a0, f0.x, acc0.x); acc0.y = fmaf(a0, f0.y, acc0.y);
                acc0.z = fmaf(a0, f1.x, acc0.z); acc0.w = fmaf(a0, f1.y, acc0.w);
                acc1.x = fmaf(a0, f2.x, acc1.x); acc1.y = fmaf(a0, f2.y, acc1.y);
                acc1.z = fmaf(a0, f3.x, acc1.z); acc1.w = fmaf(a0, f3.y, acc1.w);
            }
            {
                half2* hh = (half2*)&hv1;
                float2 f0 = __half22float2(hh[0]);
                float2 f1 = __half22float2(hh[1]);
                float2 f2 = __half22float2(hh[2]);
                float2 f3 = __half22float2(hh[3]);
                acc0.x = fmaf(a1, f0.x, acc0.x); acc0.y = fmaf(a1, f0.y, acc0.y);
                acc0.z = fmaf(a1, f1.x, acc0.z); acc0.w = fmaf(a1, f1.y, acc0.w);
                acc1.x = fmaf(a1, f2.x, acc1.x); acc1.y = fmaf(a1, f2.y, acc1.y);
                acc1.z = fmaf(a1, f3.x, acc1.z); acc1.w = fmaf(a1, f3.y, acc1.w);
            }
        }
        if (j < m) {
            int   s0 = __shfl_sync(FULL, s,  j, 8);
            float a0 = __shfl_sync(FULL, ex, j, 8);
            uint4 hv0 = __ldg((const uint4*)(hs + (size_t)s0 * CDIM) + part);
            half2* hh = (half2*)&hv0;
            float2 f0 = __half22float2(hh[0]);
            float2 f1 = __half22float2(hh[1]);
            float2 f2 = __half22float2(hh[2]);
            float2 f3 = __half22float2(hh[3]);
            acc0.x = fmaf(a0, f0.x, acc0.x); acc0.y = fmaf(a0, f0.y, acc0.y);
            acc0.z = fmaf(a0, f1.x, acc0.z); acc0.w = fmaf(a0, f1.y, acc0.w);
            acc1.x = fmaf(a0, f2.x, acc1.x); acc1.y = fmaf(a0, f2.y, acc1.y);
            acc1.z = fmaf(a0, f3.x, acc1.z); acc1.w = fmaf(a0, f3.y, acc1.w);
        }
    }
    // deferred den reduction over the 8-lane group
    float den = exsum;
    #pragma unroll
    for (int off = 4; off > 0; off >>= 1) den += __shfl_xor_sync(FULL, den, off, 8);

    float inv = (den > 0.f) ? (1.f / den) : 0.f;
    res0.x = fmaf(acc0.x, inv, res0.x); res0.y = fmaf(acc0.y, inv, res0.y);
    res0.z = fmaf(acc0.z, inv, res0.z); res0.w = fmaf(acc0.w, inv, res0.w);
    res1.x = fmaf(acc1.x, inv, res1.x); res1.y = fmaf(acc1.y, inv, res1.y);
    res1.z = fmaf(acc1.z, inv, res1.z); res1.w = fmaf(acc1.w, inv, res1.w);

    if (ELUOUT) {
        res0.x = elu1(res0.x); res0.y = elu1(res0.y);
        res0.z = elu1(res0.z); res0.w = elu1(res0.w);
        res1.x = elu1(res1.x); res1.y = elu1(res1.y);
        res1.z = elu1(res1.z); res1.w = elu1(res1.w);
    }
    if (rowvalid) {
        if (sizeof(TOUT) == 4) {    // fp32 output (final layer)
            float4* op = (float4*)((float*)out + (size_t)myrow * CDIM);
            op[part * 2]     = res0;
            op[part * 2 + 1] = res1;
        } else {                    // fp16 output (intermediate)
            half2 p0 = __float22half2_rn(make_float2(res0.x, res0.y));
            half2 p1 = __float22half2_rn(make_float2(res0.z, res0.w));
            half2 p2 = __float22half2_rn(make_float2(res1.x, res1.y));
            half2 p3 = __float22half2_rn(make_float2(res1.z, res1.w));
            uint4 hv;
            hv.x = *reinterpret_cast<unsigned*>(&p0);
            hv.y = *reinterpret_cast<unsigned*>(&p1);
            hv.z = *reinterpret_cast<unsigned*>(&p2);
            hv.w = *reinterpret_cast<unsigned*>(&p3);
            ((uint4*)((__half*)out + (size_t)myrow * CDIM))[part] = hv;
        }
    }
}

// merged GAT: warps [0,nwP) = person-dst conv (conv1); [nwP, ...) = product-dst (conv0)
template <bool ELUOUT, typename TOUT>
__global__ __launch_bounds__(256) void gat2_kernel(
    const int* __restrict__ rowP, const int* __restrict__ cntP, const int* __restrict__ ssrc1,
    const float* __restrict__ alsQ, const float* __restrict__ aldP,
    const __half* __restrict__ hsQ, const float* __restrict__ biasP,
    TOUT* __restrict__ outP, int nwP,
    const int* __restrict__ rowQ, const int* __restrict__ cntQ, const int* __restrict__ ssrc0,
    const float* __restrict__ alsP, const float* __restrict__ aldQ,
    const __half* __restrict__ hsP, const float* __restrict__ biasQ,
    TOUT* __restrict__ outQ)
{
    int w = (blockIdx.x * blockDim.x + threadIdx.x) >> 5;
    if (w < nwP) {
        gat_body<ELUOUT, TOUT>(rowP, cntP, ssrc1, alsQ, aldP, hsQ, biasP, outP, NP, w);
    } else {
        gat_body<ELUOUT, TOUT>(rowQ, cntQ, ssrc0, alsP, aldQ, hsP, biasQ, outQ, NQ, w - nwP);
    }
}

// ------------------------- host orchestration -------------------------
extern "C" void kernel_launch(void* const* d_in, const int* in_sizes, int n_in,
                              void* d_out, int out_size)
{
    const float* xp   = (const float*)d_in[0];
    const float* xq   = (const float*)d_in[1];
    const int*   pv_s = (const int*)d_in[2];
    const int*   pv_d = (const int*)d_in[3];
    const int*   vp_s = (const int*)d_in[4];
    const int*   vp_d = (const int*)d_in[5];
    const float* Wsrc = (const float*)d_in[6];
    const float* Wdst = (const float*)d_in[7];
    const float* asrc = (const float*)d_in[8];
    const float* adst = (const float*)d_in[9];
    const float* bias = (const float*)d_in[10];
    int E = in_sizes[2];

    __half *hsP, *hsQ, *hp1, *hq1;
    float *alsP, *aldP, *alsQ, *aldQ, *wvec;
    int *cntQ, *cntP, *rowQ, *rowP, *curQ, *curP, *partQ, *partP, *ssrc0, *ssrc1;
    cudaGetSymbolAddress((void**)&hsP,   g_hsP);
    cudaGetSymbolAddress((void**)&hsQ,   g_hsQ);
    cudaGetSymbolAddress((void**)&hp1,   g_hp1);
    cudaGetSymbolAddress((void**)&hq1,   g_hq1);
    cudaGetSymbolAddress((void**)&alsP,  g_alsP);
    cudaGetSymbolAddress((void**)&aldP,  g_aldP);
    cudaGetSymbolAddress((void**)&alsQ,  g_alsQ);
    cudaGetSymbolAddress((void**)&aldQ,  g_aldQ);
    cudaGetSymbolAddress((void**)&wvec,  g_wvec);
    cudaGetSymbolAddress((void**)&cntQ,  g_cntQ);
    cudaGetSymbolAddress((void**)&cntP,  g_cntP);
    cudaGetSymbolAddress((void**)&rowQ,  g_rowQ);
    cudaGetSymbolAddress((void**)&rowP,  g_rowP);
    cudaGetSymbolAddress((void**)&curQ,  g_curQ);
    cudaGetSymbolAddress((void**)&curP,  g_curP);
    cudaGetSymbolAddress((void**)&partQ, g_partQ);
    cudaGetSymbolAddress((void**)&partP, g_partP);
    cudaGetSymbolAddress((void**)&ssrc0, g_ssrc0);
    cudaGetSymbolAddress((void**)&ssrc1, g_ssrc1);

    float* outp = (float*)d_out;
    float* outq = (float*)d_out + (size_t)NP * CDIM;

    const int gP = (NP + 127) / 128, gQ = (NQ + 127) / 128;
    const int nwP = (NP + 3) / 4, nwQ = (NQ + 3) / 4;
    const unsigned gG = (unsigned)(((long)(nwP + nwQ) * 32 + 255) / 256);
    const unsigned gE2 = (2 * E + 255) / 256;

    // side stream + events (host resources, created once; no device allocs)
    static cudaStream_t sideS = nullptr;
    static cudaEvent_t evFork = nullptr, evCsr = nullptr;
    if (sideS == nullptr) {
        cudaStreamCreateWithFlags(&sideS, cudaStreamNonBlocking);
        cudaEventCreateWithFlags(&evFork, cudaEventDisableTiming);
        cudaEventCreateWithFlags(&evCsr,  cudaEventDisableTiming);
    }
    cudaStream_t s0 = 0;   // origin (harness-captured) stream

    // fork: CSR build chain on side stream (independent of GEMM-L0)
    cudaEventRecord(evFork, s0);
    cudaStreamWaitEvent(sideS, evFork, 0);
    cudaMemsetAsync(cntQ, 0, (size_t)NQPAD * sizeof(int), sideS);
    cudaMemsetAsync(cntP, 0, (size_t)NPPAD * sizeof(int), sideS);
    hist_kernel<<<gE2, 256, 0, sideS>>>(pv_d, vp_d, cntQ, cntP, E);
    scan_local2_kernel<<<MQ + MP, 256, 0, sideS>>>(cntQ, rowQ, partQ, cntP, rowP, partP);
    scan_part2_kernel<<<2, 1024, 0, sideS>>>(partQ, partP);
    scan_add2_kernel<<<(NQPAD + NPPAD + 255) / 256, 256, 0, sideS>>>(rowQ, partQ, curQ,
                                                                     rowP, partP, curP);
    scatter_kernel<<<gE2, 256, 0, sideS>>>(pv_s, pv_d, vp_s, vp_d, curQ, curP, ssrc0, ssrc1, E);
    cudaEventRecord(evCsr, sideS);

    // main: wvecs + layer-0 GEMM (overlaps the CSR chain)
    wvec4_kernel<<<1, 256, 0, s0>>>(Wdst, adst, wvec);
    gemm2_kernel<false, float><<<gP + gQ, 128, 0, s0>>>(
        xp, Wsrc + 0 * 4096, asrc + 0 * 64, wvec + 64, hsP, alsP, aldP, gP,
        xq, Wsrc + 1 * 4096, asrc + 1 * 64, wvec,      hsQ, alsQ, aldQ);

    // join: gat needs both the CSR and GEMM-L0 results
    cudaStreamWaitEvent(s0, evCsr, 0);
    gat2_kernel<false, __half><<<gG, 256, 0, s0>>>(
        rowP, cntP, ssrc1, alsQ, aldP, hsQ, bias + 1 * 64, hp1, nwP,
        rowQ, cntQ, ssrc0, alsP, aldQ, hsP, bias + 0 * 64, hq1);

    // ---- layer 1: fp16 intermediates (ELU on load) -> fp32 outputs (ELU on store) ----
    gemm2_kernel<true, __half><<<gP + gQ, 128, 0, s0>>>(
        hp1, Wsrc + 2 * 4096, asrc + 2 * 64, wvec + 128 + 64, hsP, alsP, aldP, gP,
        hq1, Wsrc + 3 * 4096, asrc + 3 * 64, wvec + 128,      hsQ, alsQ, aldQ);
    gat2_kernel<true, float><<<gG, 256, 0, s0>>>(
        rowP, cntP, ssrc1, alsQ, aldP, hsQ, bias + 3 * 64, outp, nwP,
        rowQ, cntQ, ssrc0, alsP, aldQ, hsP, bias + 2 * 64, outq);
}